// round 7
// baseline (speedup 1.0000x reference)
#include <cuda_runtime.h>
#include <math.h>
#include <stdint.h>

// ---------------- problem constants ----------------
#define TWO_B 512
#define BHALF 256
#define DDIM  512
#define NCLS  100000
#define SCALE 30.0f
#define S_LOG2E 43.280851226668914f  // 30 * log2(e)
#define COS_M 0.8775825618903728f
#define SIN_M 0.4794255386042030f
#define TH   (-0.8775825618903728f)
#define MMRG  0.2397127693021015f

// ---------------- GEMM tiling ----------------
#define MT      128                   // rows per CTA
#define NT      128                   // classes per CTA
#define NTILES  782                   // ceil(NCLS/NT)
#define NPART   784
#define KC      32                    // K elems per chunk
#define NCHUNK  16
#define ROWB    80                    // bf16 smem row pitch (conflict-free)
#define BFPITCH 144                   // fp32 B smem row pitch (16B aligned)

// smem layout (bytes)
#define A_OFF   0
#define A_STG   (MT * ROWB)                    // 10240, 4 stages
#define BF_OFF  (4 * A_STG)                    // 40960
#define BF_STG  (NT * BFPITCH)                 // 18432, 3 stages
#define BB_OFF  (BF_OFF + 3 * BF_STG)          // 96256 : bf16 B buffer (1)
#define WV_OFF  (BB_OFF + NT * ROWB)           // 106496 : winv[128]
#define SR_OFF  (WV_OFF + NT * 4)              // 107008 : sRowP[4][128]
#define SMEM_BYTES (SR_OFF + 4 * MT * 4)       // 109056

// ---------------- device scratch ----------------
__device__ __align__(16) uint16_t g_embn[TWO_B * DDIM];      // normalized emb, bf16
__device__ float g_part[TWO_B * NPART];
__device__ float g_coslab[TWO_B];
__device__ float g_nll[TWO_B];

// ---------------- helpers ----------------
__device__ __forceinline__ uint32_t smem_u32(const void* p) {
    uint32_t a;
    asm("{ .reg .u64 t; cvta.to.shared.u64 t, %1; cvt.u32.u64 %0, t; }" : "=r"(a) : "l"(p));
    return a;
}
__device__ __forceinline__ void cp16(uint32_t dst, const void* src) {
    asm volatile("cp.async.cg.shared.global [%0], [%1], 16;" :: "r"(dst), "l"(src));
}
__device__ __forceinline__ void cp_commit() { asm volatile("cp.async.commit_group;"); }
__device__ __forceinline__ void cp_wait2()  { asm volatile("cp.async.wait_group 2;"); }

__device__ __forceinline__ uint32_t pack_bf16x2(float lo, float hi) {
    uint32_t r;
    asm("cvt.rn.bf16x2.f32 %0, %1, %2;" : "=r"(r) : "f"(hi), "f"(lo));
    return r;
}
__device__ __forceinline__ void ldm_x4(uint32_t* r, uint32_t addr) {
    asm volatile("ldmatrix.sync.aligned.m8n8.x4.shared.b16 {%0,%1,%2,%3}, [%4];"
                 : "=r"(r[0]), "=r"(r[1]), "=r"(r[2]), "=r"(r[3]) : "r"(addr));
}
__device__ __forceinline__ void mma_bf16(float* d, const uint32_t* a, const uint32_t* b) {
    asm volatile(
        "mma.sync.aligned.m16n8k16.row.col.f32.bf16.bf16.f32 "
        "{%0,%1,%2,%3}, {%4,%5,%6,%7}, {%8,%9}, {%0,%1,%2,%3};"
        : "+f"(d[0]), "+f"(d[1]), "+f"(d[2]), "+f"(d[3])
        : "r"(a[0]), "r"(a[1]), "r"(a[2]), "r"(a[3]), "r"(b[0]), "r"(b[1]));
}
__device__ __forceinline__ float4 lds128(uint32_t a) {
    float4 v;
    asm volatile("ld.shared.v4.f32 {%0,%1,%2,%3}, [%4];"
                 : "=f"(v.x), "=f"(v.y), "=f"(v.z), "=f"(v.w) : "r"(a));
    return v;
}
__device__ __forceinline__ void sts128(uint32_t a, uint32_t x, uint32_t y, uint32_t z, uint32_t w) {
    asm volatile("st.shared.v4.b32 [%0], {%1,%2,%3,%4};" :: "r"(a), "r"(x), "r"(y), "r"(z), "r"(w));
}

// ============================================================
// Kernel A: normalize embeddings -> bf16
// ============================================================
__global__ void k_norm_emb(const float* __restrict__ img,
                           const float* __restrict__ prof) {
    int n = blockIdx.x;
    const float* src = (n < BHALF) ? (img + (size_t)n * DDIM)
                                   : (prof + (size_t)(n - BHALF) * DDIM);
    __shared__ float wsum[8];
    __shared__ float srinv;
    float ss = 0.f;
    for (int d = threadIdx.x; d < DDIM; d += blockDim.x) {
        float v = src[d];
        ss += v * v;
    }
    #pragma unroll
    for (int o = 16; o; o >>= 1) ss += __shfl_xor_sync(0xffffffffu, ss, o);
    if ((threadIdx.x & 31) == 0) wsum[threadIdx.x >> 5] = ss;
    __syncthreads();
    if (threadIdx.x == 0) {
        float t = 0.f;
        #pragma unroll
        for (int w = 0; w < 8; w++) t += wsum[w];
        srinv = rsqrtf(t);
    }
    __syncthreads();
    float rinv = srinv;
    for (int p = threadIdx.x; p < DDIM / 2; p += blockDim.x) {
        float a = src[p * 2] * rinv, b = src[p * 2 + 1] * rinv;
        ((uint32_t*)g_embn)[(size_t)n * (DDIM / 2) + p] = pack_bf16x2(a, b);
    }
}

// ============================================================
// Kernel B: bf16 mma.sync GEMM with fused fp32->bf16 weight
//   conversion + norm + exp epilogue.
//   CTA 128 rows x 128 classes, 256 threads, 2 CTAs/SM.
// ============================================================
__global__ void __launch_bounds__(256, 2)
k_main(const float* __restrict__ weight, const long long* __restrict__ label) {
    extern __shared__ char smem[];
    const uint32_t sb = smem_u32(smem);
    const int tid   = threadIdx.x;
    const int lane  = tid & 31;
    const int wrp   = tid >> 5;
    const int warpM = wrp & 1;     // 0..1 (64 rows each)
    const int warpN = wrp >> 1;    // 0..3 (32 cols each)
    const int g     = lane >> 2;
    const int tig   = lane & 3;

    const int m0   = blockIdx.x * MT;
    const int col0 = blockIdx.y * NT;

    float acc[4][4][4];
    #pragma unroll
    for (int mt = 0; mt < 4; mt++)
        #pragma unroll
        for (int nt = 0; nt < 4; nt++)
            #pragma unroll
            for (int e = 0; e < 4; e++) acc[mt][nt][e] = 0.f;

    // ldmatrix per-lane offsets
    const uint32_t a_lo = (uint32_t)((warpM * 64 + (lane & 15)) * ROWB + (lane >> 4) * 16);
    const uint32_t b_lo = sb + BB_OFF
        + (uint32_t)((warpN * 32 + (lane & 7) + ((lane >> 4) << 3)) * ROWB
                     + (((lane >> 3) & 1) << 4));

    // conversion mapping: thread owns row cr = tid>>1, half ch = tid&1 (16 floats)
    const int cr = tid >> 1, ch = tid & 1;
    const uint32_t cv_src = sb + BF_OFF + (uint32_t)(cr * BFPITCH + ch * 64);
    const uint32_t cv_dst = sb + BB_OFF + (uint32_t)(cr * ROWB + ch * 32);

    // ---- chunk loader ----
    auto load_chunk = [&](int c) {
        const int stA = c & 3, stB = c % 3;
        #pragma unroll
        for (int i = 0; i < 2; i++) {   // A bf16: 128 rows x 4 = 512 cp16
            int idx = i * 256 + tid;
            int r = idx >> 2, j = idx & 3;
            cp16(sb + A_OFF + (uint32_t)(stA * A_STG + r * ROWB + j * 16),
                 g_embn + (size_t)(m0 + r) * DDIM + c * KC + j * 8);
        }
        #pragma unroll
        for (int i = 0; i < 4; i++) {   // B fp32: 128 rows x 8 = 1024 cp16
            int idx = i * 256 + tid;
            int r = idx >> 3, j = idx & 7;
            int crow = col0 + r; if (crow >= NCLS) crow = NCLS - 1;
            cp16(sb + BF_OFF + (uint32_t)(stB * BF_STG + r * BFPITCH + j * 16),
                 weight + (size_t)crow * DDIM + c * KC + j * 4);
        }
    };

    load_chunk(0); cp_commit();
    load_chunk(1); cp_commit();
    load_chunk(2); cp_commit();

    float wsq = 0.f;

    for (int c = 0; c < NCHUNK; c++) {
        const int stA = c & 3, stB = c % 3;
        cp_wait2();
        __syncthreads();                 // chunk c resident; prev bb reads done

        // ---- convert B fp32 (stage stB) -> bb, accumulate sumsq ----
        {
            const uint32_t src = cv_src + (uint32_t)stB * BF_STG;
            float4 v0 = lds128(src);
            float4 v1 = lds128(src + 16);
            float4 v2 = lds128(src + 32);
            float4 v3 = lds128(src + 48);
            wsq = fmaf(v0.x, v0.x, fmaf(v0.y, v0.y, fmaf(v0.z, v0.z, fmaf(v0.w, v0.w, wsq))));
            wsq = fmaf(v1.x, v1.x, fmaf(v1.y, v1.y, fmaf(v1.z, v1.z, fmaf(v1.w, v1.w, wsq))));
            wsq = fmaf(v2.x, v2.x, fmaf(v2.y, v2.y, fmaf(v2.z, v2.z, fmaf(v2.w, v2.w, wsq))));
            wsq = fmaf(v3.x, v3.x, fmaf(v3.y, v3.y, fmaf(v3.z, v3.z, fmaf(v3.w, v3.w, wsq))));
            sts128(cv_dst,
                   pack_bf16x2(v0.x, v0.y), pack_bf16x2(v0.z, v0.w),
                   pack_bf16x2(v1.x, v1.y), pack_bf16x2(v1.z, v1.w));
            sts128(cv_dst + 16,
                   pack_bf16x2(v2.x, v2.y), pack_bf16x2(v2.z, v2.w),
                   pack_bf16x2(v3.x, v3.y), pack_bf16x2(v3.z, v3.w));
        }
        __syncthreads();                 // bb ready; fp32 stB consumed

        const uint32_t aB = sb + A_OFF + (uint32_t)stA * A_STG + a_lo;

        #pragma unroll
        for (int ks = 0; ks < 2; ks++) {
            uint32_t aF[4][4];
            #pragma unroll
            for (int mt = 0; mt < 4; mt++)
                ldm_x4(aF[mt], aB + ks * 32 + (uint32_t)mt * 16 * ROWB);
            uint32_t bF[2][4];
            #pragma unroll
            for (int p = 0; p < 2; p++)
                ldm_x4(bF[p], b_lo + ks * 32 + (uint32_t)p * 16 * ROWB);
            #pragma unroll
            for (int mt = 0; mt < 4; mt++)
                #pragma unroll
                for (int nt = 0; nt < 4; nt++)
                    mma_bf16(acc[mt][nt], aF[mt], &bF[nt >> 1][(nt & 1) * 2]);
        }

        if (c + 3 < NCHUNK) { load_chunk(c + 3); }
        cp_commit();
    }

    // winv: combine the two half-row sums (threads 2r, 2r+1)
    {
        float o = __shfl_xor_sync(0xffffffffu, wsq, 1);
        if (ch == 0) ((float*)(smem + WV_OFF))[cr] = rsqrtf(wsq + o);
    }
    __syncthreads();

    // ---- epilogue: exp row-sums + label gather ----
    const float* s_wv = (const float*)(smem + WV_OFF);
    float* sRowP = (float*)(smem + SR_OFF);

    #pragma unroll
    for (int mt = 0; mt < 4; mt++) {
        const int lrow0 = warpM * 64 + mt * 16 + g;
        const int grow0 = m0 + lrow0;
        const int grow1 = grow0 + 8;
        const int lab0 = (int)label[grow0 & 255];
        const int lab1 = (int)label[grow1 & 255];
        float sum0 = 0.f, sum1 = 0.f;
        #pragma unroll
        for (int nt = 0; nt < 4; nt++) {
            #pragma unroll
            for (int e = 0; e < 2; e++) {
                const int cl = warpN * 32 + nt * 8 + tig * 2 + e;
                const int cc = col0 + cl;
                const float wv = s_wv[cl];
                const float c0 = acc[mt][nt][e]     * wv;
                const float c1 = acc[mt][nt][2 + e] * wv;
                if (cc < NCLS) {
                    sum0 += exp2f(c0 * S_LOG2E);
                    sum1 += exp2f(c1 * S_LOG2E);
                    if (cc == lab0) g_coslab[grow0] = c0;
                    if (cc == lab1) g_coslab[grow1] = c1;
                }
            }
        }
        sum0 += __shfl_xor_sync(0xffffffffu, sum0, 1);
        sum0 += __shfl_xor_sync(0xffffffffu, sum0, 2);
        sum1 += __shfl_xor_sync(0xffffffffu, sum1, 1);
        sum1 += __shfl_xor_sync(0xffffffffu, sum1, 2);
        if (tig == 0) {
            sRowP[warpN * MT + lrow0]     = sum0;
            sRowP[warpN * MT + lrow0 + 8] = sum1;
        }
    }
    __syncthreads();
    if (tid < MT) {
        float s = sRowP[tid] + sRowP[MT + tid] + sRowP[2 * MT + tid] + sRowP[3 * MT + tid];
        g_part[(size_t)(m0 + tid) * NPART + blockIdx.y] = s;
    }
}

// ============================================================
// Kernel C1: per-row reduce + margin
// ============================================================
__global__ void k_final1(void) {
    int n = blockIdx.x;
    float s = 0.f;
    for (int t = threadIdx.x; t < NTILES; t += 128)
        s += g_part[(size_t)n * NPART + t];
    __shared__ float wsum[4];
    #pragma unroll
    for (int o = 16; o; o >>= 1) s += __shfl_xor_sync(0xffffffffu, s, o);
    if ((threadIdx.x & 31) == 0) wsum[threadIdx.x >> 5] = s;
    __syncthreads();
    if (threadIdx.x == 0) {
        float tot = wsum[0] + wsum[1] + wsum[2] + wsum[3];
        float cosl = g_coslab[n];
        float sine = sqrtf(fminf(fmaxf(1.f - cosl * cosl, 0.f), 1.f));
        float phi = cosl * COS_M - sine * SIN_M;
        if (!(cosl > TH)) phi = cosl - MMRG;
        float total = tot - exp2f(cosl * S_LOG2E) + exp2f(phi * S_LOG2E);
        g_nll[n] = logf(total) - SCALE * phi;
    }
}

// ============================================================
// Kernel C2: mean
// ============================================================
__global__ void k_final2(float* __restrict__ out) {
    int n = threadIdx.x;
    float v = g_nll[n];
    __shared__ float wsum[16];
    #pragma unroll
    for (int o = 16; o; o >>= 1) v += __shfl_xor_sync(0xffffffffu, v, o);
    if ((n & 31) == 0) wsum[n >> 5] = v;
    __syncthreads();
    if (n == 0) {
        float t = 0.f;
        #pragma unroll
        for (int w = 0; w < 16; w++) t += wsum[w];
        out[0] = t / (float)TWO_B;
    }
}

// ============================================================
// launch
// ============================================================
extern "C" void kernel_launch(void* const* d_in, const int* in_sizes, int n_in,
                              void* d_out, int out_size) {
    const float*     img  = (const float*)d_in[0];
    const float*     prof = (const float*)d_in[1];
    const float*     w    = (const float*)d_in[2];
    const long long* lab  = (const long long*)d_in[3];
    float* out = (float*)d_out;

    cudaFuncSetAttribute(k_main, cudaFuncAttributeMaxDynamicSharedMemorySize, SMEM_BYTES);

    k_norm_emb<<<TWO_B, 256>>>(img, prof);
    dim3 grid(4, NTILES);                 // M fastest -> weight L2 reuse
    k_main<<<grid, 256, SMEM_BYTES>>>(w, lab);
    k_final1<<<TWO_B, 128>>>();
    k_final2<<<1, TWO_B>>>(out);
}